// round 2
// baseline (speedup 1.0000x reference)
#include <cuda_runtime.h>

// JointIntegralRegressor: soft-argmax over [16,24,64,64,64] fp32 heatmaps.
// Single fused kernel: streaming exp-moment reduction per chunk, last
// chunk-CTA per slice combines partials (fixed order -> deterministic)
// and writes the final 3 coords. Self-resetting counters keep the kernel
// graph-replayable with no extra launches.

#define DIM_W 64
#define DIM_H 64
#define DIM_D 64
#define SLICES 384                           // 16*24
#define SLICE_ELEMS (DIM_D * DIM_H * DIM_W)  // 262144
#define CHUNKS_PER_SLICE 8
#define CHUNK_ELEMS (SLICE_ELEMS / CHUNKS_PER_SLICE)   // 32768
#define NCHUNKS (SLICES * CHUNKS_PER_SLICE)            // 3072
#define P1_THREADS 256
#define V4_PER_THREAD (CHUNK_ELEMS / 4 / P1_THREADS)   // 32

// Scratch: per-chunk partial moments (s, sx, sy, sz) + per-slice arrival count.
__device__ float4 g_partials[NCHUNKS];
__device__ unsigned int g_cnt[SLICES];   // zero-init; self-resetting

__global__ __launch_bounds__(P1_THREADS)
void jir_fused(const float* __restrict__ in, float* __restrict__ out) {
    const int chunk = blockIdx.x;
    const int slice = chunk >> 3;            // /CHUNKS_PER_SLICE
    const int tid = threadIdx.x;

    const float4* __restrict__ in4 =
        reinterpret_cast<const float4*>(in) + (long long)chunk * (CHUNK_ELEMS / 4);
    const int elem0 = (chunk & (CHUNKS_PER_SLICE - 1)) * CHUNK_ELEMS;

    float s = 0.f, sx = 0.f, sy = 0.f, sz = 0.f;

    #pragma unroll 4
    for (int it = 0; it < V4_PER_THREAD; ++it) {
        const int idx4 = it * P1_THREADS + tid;     // float4 index in chunk
        const float4 v = in4[idx4];

        const int e  = elem0 + idx4 * 4;            // element index in slice
        const float w0 = (float)(e & (DIM_W - 1));  // x of lane 0 (row-aligned)
        const int   hd = e >> 6;
        const float hf = (float)(hd & (DIM_H - 1));
        const float df = (float)(hd >> 6);

        const float e0 = __expf(v.x);
        const float e1 = __expf(v.y);
        const float e2 = __expf(v.z);
        const float e3 = __expf(v.w);

        const float sp = (e0 + e1) + (e2 + e3);
        // sum_k e_k * (w0 + k) = w0*sp + (e1 + 2*e2 + 3*e3)
        float inner = fmaf(2.f, e2, e1);
        inner       = fmaf(3.f, e3, inner);

        s  += sp;
        sx += fmaf(w0, sp, inner);
        sy  = fmaf(hf, sp, sy);
        sz  = fmaf(df, sp, sz);
    }

    // Block reduction: warp shuffle, then warp-partials through shared memory.
    #pragma unroll
    for (int off = 16; off > 0; off >>= 1) {
        s  += __shfl_down_sync(0xFFFFFFFFu, s,  off);
        sx += __shfl_down_sync(0xFFFFFFFFu, sx, off);
        sy += __shfl_down_sync(0xFFFFFFFFu, sy, off);
        sz += __shfl_down_sync(0xFFFFFFFFu, sz, off);
    }

    __shared__ float4 red[P1_THREADS / 32];
    const int warp = tid >> 5;
    const int lane = tid & 31;
    if (lane == 0) red[warp] = make_float4(s, sx, sy, sz);
    __syncthreads();

    if (tid == 0) {
        float4 acc = red[0];
        #pragma unroll
        for (int i = 1; i < P1_THREADS / 32; ++i) {
            acc.x += red[i].x;
            acc.y += red[i].y;
            acc.z += red[i].z;
            acc.w += red[i].w;
        }
        g_partials[chunk] = acc;

        // Make the partial visible, then take a ticket for this slice.
        __threadfence();
        const unsigned int old = atomicAdd(&g_cnt[slice], 1u);
        if (old == CHUNKS_PER_SLICE - 1) {
            // Last arriver: combine in fixed order (deterministic), reset counter.
            g_cnt[slice] = 0;
            float fs = 0.f, fsx = 0.f, fsy = 0.f, fsz = 0.f;
            #pragma unroll
            for (int c = 0; c < CHUNKS_PER_SLICE; ++c) {
                const float4 p = g_partials[slice * CHUNKS_PER_SLICE + c];
                fs += p.x; fsx += p.y; fsy += p.z; fsz += p.w;
            }
            const float inv = 1.0f / fs;
            const float scale = 1.0f / 64.0f;
            out[slice * 3 + 0] = fsx * inv * scale - 0.5f;
            out[slice * 3 + 1] = fsy * inv * scale - 0.5f;
            out[slice * 3 + 2] = fsz * inv * scale - 0.5f;
        }
    }
}

extern "C" void kernel_launch(void* const* d_in, const int* in_sizes, int n_in,
                              void* d_out, int out_size) {
    const float* heatmaps = (const float*)d_in[0];
    float* out = (float*)d_out;
    jir_fused<<<NCHUNKS, P1_THREADS>>>(heatmaps, out);
}

// round 3
// speedup vs baseline: 1.0047x; 1.0047x over previous
#include <cuda_runtime.h>

// JointIntegralRegressor: soft-argmax over [16,24,64,64,64] fp32 heatmaps.
// Single fused kernel: streaming exp-moment reduction per chunk; last
// chunk-CTA per slice (release/acquire ticket, NO threadfence) combines
// partials in fixed order (deterministic) and writes the 3 coords.
// Self-resetting counters keep it graph-replayable.

#define DIM_W 64
#define DIM_H 64
#define DIM_D 64
#define SLICES 384                           // 16*24
#define SLICE_ELEMS (DIM_D * DIM_H * DIM_W)  // 262144
#define CHUNKS_PER_SLICE 8
#define CHUNK_ELEMS (SLICE_ELEMS / CHUNKS_PER_SLICE)   // 32768
#define NCHUNKS (SLICES * CHUNKS_PER_SLICE)            // 3072
#define P1_THREADS 256
#define V4_PER_THREAD (CHUNK_ELEMS / 4 / P1_THREADS)   // 32

// Scratch: per-chunk partial moments (s, sx, sy, sz) + per-slice arrival count.
__device__ float4 g_partials[NCHUNKS];
__device__ unsigned int g_cnt[SLICES];   // zero-init; self-resetting

__global__ __launch_bounds__(P1_THREADS)
void jir_fused(const float* __restrict__ in, float* __restrict__ out) {
    const int chunk = blockIdx.x;
    const int slice = chunk >> 3;            // /CHUNKS_PER_SLICE
    const int tid = threadIdx.x;

    const float4* __restrict__ in4 =
        reinterpret_cast<const float4*>(in) + (long long)chunk * (CHUNK_ELEMS / 4);
    const int elem0 = (chunk & (CHUNKS_PER_SLICE - 1)) * CHUNK_ELEMS;

    float s = 0.f, sx = 0.f, sy = 0.f, sz = 0.f;

    #pragma unroll 4
    for (int it = 0; it < V4_PER_THREAD; ++it) {
        const int idx4 = it * P1_THREADS + tid;     // float4 index in chunk
        const float4 v = in4[idx4];

        const int e  = elem0 + idx4 * 4;            // element index in slice
        const float w0 = (float)(e & (DIM_W - 1));  // x of lane 0 (row-aligned)
        const int   hd = e >> 6;
        const float hf = (float)(hd & (DIM_H - 1));
        const float df = (float)(hd >> 6);

        const float e0 = __expf(v.x);
        const float e1 = __expf(v.y);
        const float e2 = __expf(v.z);
        const float e3 = __expf(v.w);

        const float sp = (e0 + e1) + (e2 + e3);
        // sum_k e_k * (w0 + k) = w0*sp + (e1 + 2*e2 + 3*e3)
        float inner = fmaf(2.f, e2, e1);
        inner       = fmaf(3.f, e3, inner);

        s  += sp;
        sx += fmaf(w0, sp, inner);
        sy  = fmaf(hf, sp, sy);
        sz  = fmaf(df, sp, sz);
    }

    // Block reduction: warp shuffle, then warp-partials through shared memory.
    #pragma unroll
    for (int off = 16; off > 0; off >>= 1) {
        s  += __shfl_down_sync(0xFFFFFFFFu, s,  off);
        sx += __shfl_down_sync(0xFFFFFFFFu, sx, off);
        sy += __shfl_down_sync(0xFFFFFFFFu, sy, off);
        sz += __shfl_down_sync(0xFFFFFFFFu, sz, off);
    }

    __shared__ float4 red[P1_THREADS / 32];
    const int warp = tid >> 5;
    const int lane = tid & 31;
    if (lane == 0) red[warp] = make_float4(s, sx, sy, sz);
    __syncthreads();

    if (tid == 0) {
        float4 acc = red[0];
        #pragma unroll
        for (int i = 1; i < P1_THREADS / 32; ++i) {
            acc.x += red[i].x;
            acc.y += red[i].y;
            acc.z += red[i].z;
            acc.w += red[i].w;
        }
        // Publish partial to L2 (bypass L1 coherence questions entirely).
        asm volatile("st.global.cg.v4.f32 [%0], {%1, %2, %3, %4};"
                     :: "l"(&g_partials[chunk]),
                        "f"(acc.x), "f"(acc.y), "f"(acc.z), "f"(acc.w)
                     : "memory");

        // Release/acquire ticket — orders the partial store before the count,
        // and the combiner's loads after all releases. No MEMBAR, no L1 flush.
        unsigned int old;
        asm volatile("atom.add.acq_rel.gpu.u32 %0, [%1], %2;"
                     : "=r"(old)
                     : "l"(&g_cnt[slice]), "r"(1u)
                     : "memory");

        if (old == CHUNKS_PER_SLICE - 1) {
            // Last arriver: combine in fixed order (deterministic), reset counter.
            g_cnt[slice] = 0;
            float fs = 0.f, fsx = 0.f, fsy = 0.f, fsz = 0.f;
            #pragma unroll
            for (int c = 0; c < CHUNKS_PER_SLICE; ++c) {
                float px, py, pz, pw;
                asm volatile("ld.global.cg.v4.f32 {%0, %1, %2, %3}, [%4];"
                             : "=f"(px), "=f"(py), "=f"(pz), "=f"(pw)
                             : "l"(&g_partials[slice * CHUNKS_PER_SLICE + c])
                             : "memory");
                fs += px; fsx += py; fsy += pz; fsz += pw;
            }
            const float inv = 1.0f / fs;
            const float scale = 1.0f / 64.0f;
            out[slice * 3 + 0] = fsx * inv * scale - 0.5f;
            out[slice * 3 + 1] = fsy * inv * scale - 0.5f;
            out[slice * 3 + 2] = fsz * inv * scale - 0.5f;
        }
    }
}

extern "C" void kernel_launch(void* const* d_in, const int* in_sizes, int n_in,
                              void* d_out, int out_size) {
    const float* heatmaps = (const float*)d_in[0];
    float* out = (float*)d_out;
    jir_fused<<<NCHUNKS, P1_THREADS>>>(heatmaps, out);
}

// round 4
// speedup vs baseline: 1.0647x; 1.0598x over previous
#include <cuda_runtime.h>

// JointIntegralRegressor: soft-argmax over [16,24,64,64,64] fp32 heatmaps.
// Two kernels (fused-atomic variant measured SLOWER in R2/R3):
//   pass1: streaming exp-moment reduction per chunk -> g_partials
//   pass2: per-slice combine (deterministic fixed order) -> out[slice*3..]
// pass2 is launched with Programmatic Dependent Launch so its launch ramp
// overlaps pass1's tail; it gridDependencySynchronize()s before reading.

#define DIM_W 64
#define DIM_H 64
#define DIM_D 64
#define SLICES 384                           // 16*24
#define SLICE_ELEMS (DIM_D * DIM_H * DIM_W)  // 262144
#define CHUNKS_PER_SLICE 8
#define CHUNK_ELEMS (SLICE_ELEMS / CHUNKS_PER_SLICE)   // 32768
#define NCHUNKS (SLICES * CHUNKS_PER_SLICE)            // 3072
#define P1_THREADS 256
#define V4_PER_THREAD (CHUNK_ELEMS / 4 / P1_THREADS)   // 32

// Scratch for per-chunk partial moments: (s, sx, sy, sz).
__device__ float4 g_partials[NCHUNKS];

__global__ __launch_bounds__(P1_THREADS)
void jir_pass1(const float* __restrict__ in) {
    const int chunk = blockIdx.x;
    const int tid = threadIdx.x;

    const float4* __restrict__ in4 =
        reinterpret_cast<const float4*>(in) + (long long)chunk * (CHUNK_ELEMS / 4);
    const int elem0 = (chunk & (CHUNKS_PER_SLICE - 1)) * CHUNK_ELEMS;

    float s = 0.f, sx = 0.f, sy = 0.f, sz = 0.f;

    #pragma unroll 4
    for (int it = 0; it < V4_PER_THREAD; ++it) {
        const int idx4 = it * P1_THREADS + tid;     // float4 index in chunk
        const float4 v = __ldcs(&in4[idx4]);        // read-once: evict-first

        const int e  = elem0 + idx4 * 4;            // element index in slice
        const float w0 = (float)(e & (DIM_W - 1));  // x of lane 0 (row-aligned)
        const int   hd = e >> 6;
        const float hf = (float)(hd & (DIM_H - 1));
        const float df = (float)(hd >> 6);

        const float e0 = __expf(v.x);
        const float e1 = __expf(v.y);
        const float e2 = __expf(v.z);
        const float e3 = __expf(v.w);

        const float sp = (e0 + e1) + (e2 + e3);
        // sum_k e_k * (w0 + k) = w0*sp + (e1 + 2*e2 + 3*e3)
        float inner = fmaf(2.f, e2, e1);
        inner       = fmaf(3.f, e3, inner);

        s  += sp;
        sx += fmaf(w0, sp, inner);
        sy  = fmaf(hf, sp, sy);
        sz  = fmaf(df, sp, sz);
    }

    // Mainloop done: let the dependent kernel start its launch ramp now.
    cudaTriggerProgrammaticLaunchCompletion();

    // Block reduction: warp shuffle, then warp-partials through shared memory.
    #pragma unroll
    for (int off = 16; off > 0; off >>= 1) {
        s  += __shfl_down_sync(0xFFFFFFFFu, s,  off);
        sx += __shfl_down_sync(0xFFFFFFFFu, sx, off);
        sy += __shfl_down_sync(0xFFFFFFFFu, sy, off);
        sz += __shfl_down_sync(0xFFFFFFFFu, sz, off);
    }

    __shared__ float4 red[P1_THREADS / 32];
    const int warp = tid >> 5;
    const int lane = tid & 31;
    if (lane == 0) red[warp] = make_float4(s, sx, sy, sz);
    __syncthreads();

    if (tid == 0) {
        float4 acc = red[0];
        #pragma unroll
        for (int i = 1; i < P1_THREADS / 32; ++i) {
            acc.x += red[i].x;
            acc.y += red[i].y;
            acc.z += red[i].z;
            acc.w += red[i].w;
        }
        g_partials[chunk] = acc;
    }
}

__global__ void jir_pass2(float* __restrict__ out) {
    // Wait for pass1 grid completion (memory visible after this returns).
    cudaGridDependencySynchronize();

    const int slice = blockIdx.x * blockDim.x + threadIdx.x;
    if (slice >= SLICES) return;

    float s = 0.f, sx = 0.f, sy = 0.f, sz = 0.f;
    #pragma unroll
    for (int c = 0; c < CHUNKS_PER_SLICE; ++c) {
        const float4 p = g_partials[slice * CHUNKS_PER_SLICE + c];
        s += p.x; sx += p.y; sy += p.z; sz += p.w;
    }

    const float inv = 1.0f / s;
    const float scale = 1.0f / 64.0f;
    out[slice * 3 + 0] = sx * inv * scale - 0.5f;
    out[slice * 3 + 1] = sy * inv * scale - 0.5f;
    out[slice * 3 + 2] = sz * inv * scale - 0.5f;
}

extern "C" void kernel_launch(void* const* d_in, const int* in_sizes, int n_in,
                              void* d_out, int out_size) {
    const float* heatmaps = (const float*)d_in[0];
    float* out = (float*)d_out;

    jir_pass1<<<NCHUNKS, P1_THREADS>>>(heatmaps);

    // PDL launch of pass2: overlaps its launch latency with pass1's tail.
    cudaLaunchAttribute attr;
    attr.id = cudaLaunchAttributeProgrammaticStreamSerialization;
    attr.val.programmaticStreamSerializationAllowed = 1;

    cudaLaunchConfig_t cfg = {};
    cfg.gridDim = dim3(3);
    cfg.blockDim = dim3(128);
    cfg.dynamicSmemBytes = 0;
    cfg.stream = 0;  // same (legacy default) stream as pass1
    cfg.attrs = &attr;
    cfg.numAttrs = 1;

    cudaLaunchKernelEx(&cfg, jir_pass2, out);
}